// round 6
// baseline (speedup 1.0000x reference)
#include <cuda_runtime.h>
#include <cuda_fp16.h>

#define NMAX 100000
#define EMAX 1600000

// ---------------- device scratch (static, no allocation) ----------------
__device__ __align__(16) int    g_deg[NMAX];     // in-edge count (no self-loop)
__device__ __align__(16) float  g_dis[NMAX];     // (deg+1)^-1/2
__device__ __align__(16) int    g_ptr[NMAX];     // CSR segment start (per target node)
__device__ __align__(16) int    g_cur[NMAX];     // fill cursor
__device__ __align__(16) int    g_src[EMAX];     // CSR adjacency: source ids grouped by target
__device__ int    g_total;                       // segment allocator
__device__ __align__(16) __half g_hwh[(size_t)NMAX * 128]; // dis-prefolded features (fp16)
__device__ __align__(16) float  g_h10[(size_t)NMAX * 10];  // width-10 prefolded features (fp32)
__device__ __align__(16) float  g_acc[(size_t)NMAX * 128]; // propagate result fp32 (width-10 L4)

// ---------------- mma / ldmatrix helpers ----------------
__device__ __forceinline__ void mma_f16(float* c, const unsigned* a, const unsigned* b) {
    asm("mma.sync.aligned.m16n8k16.row.col.f32.f16.f16.f32 "
        "{%0,%1,%2,%3}, {%4,%5,%6,%7}, {%8,%9}, {%0,%1,%2,%3};"
        : "+f"(c[0]), "+f"(c[1]), "+f"(c[2]), "+f"(c[3])
        : "r"(a[0]), "r"(a[1]), "r"(a[2]), "r"(a[3]), "r"(b[0]), "r"(b[1]));
}
__device__ __forceinline__ void ldsm_x4(unsigned* r, unsigned saddr) {
    asm volatile("ldmatrix.sync.aligned.m8n8.x4.shared.b16 {%0,%1,%2,%3}, [%4];"
                 : "=r"(r[0]), "=r"(r[1]), "=r"(r[2]), "=r"(r[3]) : "r"(saddr));
}
__device__ __forceinline__ unsigned smem_u32(const void* p) {
    return (unsigned)__cvta_generic_to_shared(p);
}

// ---------------- graph preprocessing ----------------
__global__ void k_count(const int* __restrict__ ei, int E) {
    int e = blockIdx.x * blockDim.x + threadIdx.x;
    if (e == 0) g_total = 0;
    if (e >= E) return;
    atomicAdd(&g_deg[ei[(size_t)E + e]], 1);
}

__global__ void k_alloc(int N) {
    __shared__ int s[256];
    __shared__ int base;
    int tid = threadIdx.x;
    int i = blockIdx.x * 256 + tid;
    int d = (i < N) ? g_deg[i] : 0;
    if (i < N) g_dis[i] = rsqrtf((float)(d + 1));   // +1 self-loop
    s[tid] = d;
    __syncthreads();
    #pragma unroll
    for (int off = 1; off < 256; off <<= 1) {
        int v = (tid >= off) ? s[tid - off] : 0;
        __syncthreads();
        s[tid] += v;
        __syncthreads();
    }
    if (tid == 255) base = atomicAdd(&g_total, s[255]);
    __syncthreads();
    if (i < N) {
        int p = base + s[tid] - d;
        g_ptr[i] = p;
        g_cur[i] = p;
    }
}

__global__ void k_fill(const int* __restrict__ ei, int E) {
    int e = blockIdx.x * blockDim.x + threadIdx.x;
    if (e >= E) return;
    int r = ei[e];
    int c = ei[(size_t)E + e];
    int p = atomicAdd(&g_cur[c], 1);
    g_src[p] = r;
}

// ---------------- fp16 tensor-core GEMM: g_hwh = dis .* (A' @ W), fp16 out ----------------
// A' = (mode ? relu(g_acc + bias) : Aext).  128x128 block tile, 8 warps of 32x64.
// Wt[n][k] fp16 stride 136; As[m][k] fp16 stride 136; whole K=128 resident.
#define HS 136
#define GEMM_SMEM_BYTES (2 * 128 * HS * 2)

__global__ void __launch_bounds__(256, 2) gemm128(const float* __restrict__ Aext,
                                                  const float* __restrict__ W,
                                                  const float* __restrict__ bias,
                                                  int mode, int N) {
    extern __shared__ __half smem_h[];
    __half* Wt = smem_h;               // [n][k] stride HS
    __half* As = smem_h + 128 * HS;    // [m][k] stride HS
    const float* A = mode ? g_acc : Aext;

    int tid  = threadIdx.x;
    int wid  = tid >> 5;
    int lane = tid & 31;
    int lr = lane >> 2;                // 0..7
    int lc = lane & 3;                 // 0..3
    int warp_m = (wid & 3) * 32;
    int warp_n = (wid >> 2) * 64;
    int row0 = blockIdx.x * 128;

    // stage W transposed -> Wt[n][k] fp16
    #pragma unroll 4
    for (int j = 0; j < 16; ++j) {
        int idx4 = (tid + 256 * j) * 4;
        int k = idx4 >> 7, n = idx4 & 127;
        float4 v = *(const float4*)&W[idx4];
        Wt[(n + 0) * HS + k] = __float2half(v.x);
        Wt[(n + 1) * HS + k] = __float2half(v.y);
        Wt[(n + 2) * HS + k] = __float2half(v.z);
        Wt[(n + 3) * HS + k] = __float2half(v.w);
    }
    // stage A' -> As[m][k] fp16 (bias + relu fused)
    #pragma unroll 4
    for (int j = 0; j < 16; ++j) {
        int f = tid + 256 * j;             // 0..4095
        int r = f >> 5;                    // row 0..127
        int k4 = (f & 31) * 4;             // k 0,4,..124
        int grow = row0 + r;
        float4 v = make_float4(0.f, 0.f, 0.f, 0.f);
        if (grow < N) v = *(const float4*)&A[(size_t)grow * 128 + k4];
        if (mode) {
            float4 b4 = *(const float4*)&bias[k4];
            v.x = fmaxf(v.x + b4.x, 0.f);
            v.y = fmaxf(v.y + b4.y, 0.f);
            v.z = fmaxf(v.z + b4.z, 0.f);
            v.w = fmaxf(v.w + b4.w, 0.f);
        }
        __half2 h0 = __floats2half2_rn(v.x, v.y);
        __half2 h1 = __floats2half2_rn(v.z, v.w);
        uint2 u = make_uint2(*(unsigned*)&h0, *(unsigned*)&h1);
        *(uint2*)&As[r * HS + k4] = u;
    }
    __syncthreads();

    float acc[2][8][4];
    #pragma unroll
    for (int i = 0; i < 2; ++i)
        #pragma unroll
        for (int j = 0; j < 8; ++j)
            #pragma unroll
            for (int q = 0; q < 4; ++q) acc[i][j][q] = 0.f;

    // ldmatrix base addresses (per-lane)
    unsigned a_base[2], b_base[4];
    #pragma unroll
    for (int i = 0; i < 2; ++i) {
        int row = warp_m + i * 16 + (lane & 15);
        int coladd = (lane >> 4) * 8;
        a_base[i] = smem_u32(&As[row * HS + coladd]);
    }
    #pragma unroll
    for (int jj = 0; jj < 4; ++jj) {
        int row = warp_n + jj * 16 + ((lane >> 4) << 3) + (lane & 7);
        int coladd = ((lane >> 3) & 1) * 8;
        b_base[jj] = smem_u32(&Wt[row * HS + coladd]);
    }

    #pragma unroll
    for (int ks = 0; ks < 8; ++ks) {
        unsigned af[2][4], bf[8][2];
        ldsm_x4(af[0], a_base[0] + ks * 32);
        ldsm_x4(af[1], a_base[1] + ks * 32);
        #pragma unroll
        for (int jj = 0; jj < 4; ++jj) {
            unsigned t[4];
            ldsm_x4(t, b_base[jj] + ks * 32);
            bf[2 * jj][0] = t[0]; bf[2 * jj][1] = t[1];
            bf[2 * jj + 1][0] = t[2]; bf[2 * jj + 1][1] = t[3];
        }
        #pragma unroll
        for (int i = 0; i < 2; ++i)
            #pragma unroll
            for (int j = 0; j < 8; ++j)
                mma_f16(acc[i][j], af[i], bf[j]);
    }

    // epilogue: scale by dis[row], convert to half2, store
    #pragma unroll
    for (int i = 0; i < 2; ++i) {
        int r0i = row0 + warp_m + i * 16 + lr;
        int r1i = r0i + 8;
        float d0 = (r0i < N) ? g_dis[r0i] : 0.f;
        float d1 = (r1i < N) ? g_dis[r1i] : 0.f;
        #pragma unroll
        for (int j = 0; j < 8; ++j) {
            int col = warp_n + j * 8 + lc * 2;
            if (r0i < N)
                *(__half2*)&g_hwh[(size_t)r0i * 128 + col] =
                    __floats2half2_rn(acc[i][j][0] * d0, acc[i][j][1] * d0);
            if (r1i < N)
                *(__half2*)&g_hwh[(size_t)r1i * 128 + col] =
                    __floats2half2_rn(acc[i][j][2] * d1, acc[i][j][3] * d1);
        }
    }
}

// ---------------- SpMM width 128 (fp16 in, fp32 out) ----------------
__device__ __forceinline__ void add_row(float4& s, const uint2* hp, size_t idx) {
    uint2 w = __ldg(&hp[idx]);
    float2 f0 = __half22float2(*(const __half2*)&w.x);
    float2 f1 = __half22float2(*(const __half2*)&w.y);
    s.x += f0.x; s.y += f0.y; s.z += f1.x; s.w += f1.y;
}

__global__ void spmm128(int N) {
    int warp = (blockIdx.x * blockDim.x + threadIdx.x) >> 5;
    if (warp >= N) return;
    int lane = threadIdx.x & 31;
    const uint2* hp = (const uint2*)g_hwh;       // 32 uint2 per row
    float4 s = make_float4(0.f, 0.f, 0.f, 0.f);
    add_row(s, hp, (size_t)warp * 32 + lane);    // self-loop term
    int beg = g_ptr[warp];
    int end = beg + g_deg[warp];
    int p = beg;
    for (; p + 3 < end; p += 4) {
        int s0 = __ldg(&g_src[p]);
        int s1 = __ldg(&g_src[p + 1]);
        int s2 = __ldg(&g_src[p + 2]);
        int s3 = __ldg(&g_src[p + 3]);
        add_row(s, hp, (size_t)s0 * 32 + lane);
        add_row(s, hp, (size_t)s1 * 32 + lane);
        add_row(s, hp, (size_t)s2 * 32 + lane);
        add_row(s, hp, (size_t)s3 * 32 + lane);
    }
    for (; p < end; ++p) {
        int s0 = __ldg(&g_src[p]);
        add_row(s, hp, (size_t)s0 * 32 + lane);
    }
    float di = g_dis[warp];
    s.x *= di; s.y *= di; s.z *= di; s.w *= di;
    *(float4*)&g_acc[(size_t)warp * 128 + lane * 4] = s;
}

// ---------------- layer 4 GEMM: g_h10[n] = dis[n] * (relu(g_acc[n]+b_h1) @ W_out) ----------------
__global__ void gemm_out(const float* __restrict__ W, const float* __restrict__ bias, int N) {
    __shared__ float Ws[128 * 10];
    __shared__ float bs[128];
    int tid = threadIdx.x;
    for (int i = tid; i < 1280; i += 256) Ws[i] = W[i];
    if (tid < 128) bs[tid] = bias[tid];
    __syncthreads();
    int n = blockIdx.x * 256 + tid;
    if (n >= N) return;
    float s[10];
    #pragma unroll
    for (int c = 0; c < 10; ++c) s[c] = 0.f;
    const float* a = g_acc + (size_t)n * 128;
    #pragma unroll 4
    for (int k = 0; k < 128; k += 4) {
        float4 v = *(const float4*)&a[k];
        float a0 = fmaxf(v.x + bs[k + 0], 0.f);
        float a1 = fmaxf(v.y + bs[k + 1], 0.f);
        float a2 = fmaxf(v.z + bs[k + 2], 0.f);
        float a3 = fmaxf(v.w + bs[k + 3], 0.f);
        const float* w0 = &Ws[k * 10];
        #pragma unroll
        for (int c = 0; c < 10; ++c)
            s[c] += a0 * w0[c] + a1 * w0[10 + c] + a2 * w0[20 + c] + a3 * w0[30 + c];
    }
    float dn = g_dis[n];
    float* o = g_h10 + (size_t)n * 10;
    #pragma unroll
    for (int c = 0; c < 10; ++c) o[c] = s[c] * dn;
}

// ---------------- SpMM width 10 (prefolded fp32) ----------------
__global__ void spmm10(int N) {
    int warp = (blockIdx.x * blockDim.x + threadIdx.x) >> 5;
    if (warp >= N) return;
    int lane = threadIdx.x & 31;
    int grp = lane / 10;
    int c = lane - grp * 10;
    bool active = lane < 30;
    float s = 0.f;
    if (active && grp == 0) s = g_h10[(size_t)warp * 10 + c];     // self-loop term
    int beg = g_ptr[warp];
    int m = g_deg[warp];
    for (int p = 0; p < m; p += 3) {
        int e = p + grp;
        if (active && e < m) {
            int src = __ldg(&g_src[beg + e]);
            s += g_h10[(size_t)src * 10 + c];
        }
    }
    float s1 = __shfl_sync(0xffffffffu, s, lane + 10);
    float s2 = __shfl_sync(0xffffffffu, s, lane + 20);
    if (lane < 10) g_acc[(size_t)warp * 10 + lane] = (s + s1 + s2) * g_dis[warp];
}

// ---------------- mean pooling ----------------
__device__ __forceinline__ int lower_bound_i(const int* a, int n, int key) {
    int lo = 0, hi = n;
    while (lo < hi) {
        int mid = (lo + hi) >> 1;
        if (a[mid] < key) lo = mid + 1; else hi = mid;
    }
    return lo;
}

__global__ void pool(const int* __restrict__ batch, const float* __restrict__ b_out,
                     float* __restrict__ out, int N) {
    __shared__ float sred[128];
    int g = blockIdx.x;
    int t = threadIdx.x;
    int lo = lower_bound_i(batch, N, g);
    int hi = lower_bound_i(batch, N, g + 1);
    float s = 0.f;
    if (t < 120) {
        int c = t / 12, sl = t % 12;
        for (int i = lo + sl; i < hi; i += 12) s += g_acc[(size_t)i * 10 + c];
    }
    sred[t] = s;
    __syncthreads();
    if (t < 10) {
        float tot = 0.f;
        #pragma unroll
        for (int j = 0; j < 12; ++j) tot += sred[t * 12 + j];
        float cnt = (float)(hi - lo);
        out[g * 10 + t] = (tot + cnt * b_out[t]) / fmaxf(cnt, 1.f);
    }
}

// ---------------- launcher ----------------
extern "C" void kernel_launch(void* const* d_in, const int* in_sizes, int n_in,
                              void* d_out, int out_size) {
    const float* x      = (const float*)d_in[0];
    const int*   ei     = (const int*)d_in[1];
    const int*   batch  = (const int*)d_in[2];
    const float* W_init = (const float*)d_in[3];
    const float* b_init = (const float*)d_in[4];
    const float* W_h0   = (const float*)d_in[5];
    const float* b_h0   = (const float*)d_in[6];
    const float* W_h1   = (const float*)d_in[7];
    const float* b_h1   = (const float*)d_in[8];
    const float* W_out  = (const float*)d_in[9];
    const float* b_out  = (const float*)d_in[10];
    float* out = (float*)d_out;

    int N = in_sizes[0] / 128;
    int E = in_sizes[1] / 2;

    int nb = (N + 255) / 256;
    int eb = (E + 255) / 256;
    int gb = (N + 127) / 128;
    int sb = (N + 7) / 8;

    static int* deg_ptr = nullptr;
    if (!deg_ptr) {
        cudaGetSymbolAddress((void**)&deg_ptr, g_deg);
        cudaFuncSetAttribute(gemm128, cudaFuncAttributeMaxDynamicSharedMemorySize, GEMM_SMEM_BYTES);
    }

    cudaMemsetAsync(deg_ptr, 0, (size_t)N * sizeof(int));
    k_count<<<eb, 256>>>(ei, E);
    k_alloc<<<nb, 256>>>(N);
    k_fill<<<eb, 256>>>(ei, E);

    gemm128<<<gb, 256, GEMM_SMEM_BYTES>>>(x, W_init, b_init, 0, N);
    spmm128<<<sb, 256>>>(N);
    gemm128<<<gb, 256, GEMM_SMEM_BYTES>>>(nullptr, W_h0, b_init, 1, N);
    spmm128<<<sb, 256>>>(N);
    gemm128<<<gb, 256, GEMM_SMEM_BYTES>>>(nullptr, W_h1, b_h0, 1, N);
    spmm128<<<sb, 256>>>(N);
    gemm_out<<<nb, 256>>>(W_out, b_h1, N);
    spmm10<<<sb, 256>>>(N);
    pool<<<512, 128>>>(batch, b_out, out, N);
}

// round 7
// speedup vs baseline: 1.1478x; 1.1478x over previous
#include <cuda_runtime.h>
#include <cuda_fp16.h>

#define NMAX 100000
#define EMAX 1600000

// ---------------- device scratch (static, no allocation) ----------------
__device__ __align__(16) int    g_deg[NMAX];     // in-edge count (no self-loop)
__device__ __align__(16) float  g_dis[NMAX];     // (deg+1)^-1/2
__device__ __align__(16) int    g_ptr[NMAX];     // CSR segment start (per target node)
__device__ __align__(16) int    g_cur[NMAX];     // fill cursor
__device__ __align__(16) int    g_src[EMAX];     // CSR adjacency: source ids grouped by target
__device__ int    g_total;                       // segment allocator
__device__ __align__(16) __half g_hwh[(size_t)NMAX * 128]; // dis-prefolded features (fp16)
__device__ __align__(16) __half g_af[(size_t)NMAX * 128];  // activated features relu(acc+bias) fp16
__device__ __align__(16) float  g_h10[(size_t)NMAX * 10];  // width-10 prefolded features
__device__ __align__(16) float  g_a10[(size_t)NMAX * 10];  // width-10 propagate result

// ---------------- helpers ----------------
__device__ __forceinline__ float tf32r(float v) {
    unsigned r; asm("cvt.rna.tf32.f32 %0, %1;" : "=r"(r) : "f"(v));
    return __uint_as_float(r);
}
__device__ __forceinline__ void mma_tf32(float* c, const unsigned* a, const unsigned* b) {
    asm("mma.sync.aligned.m16n8k8.row.col.f32.tf32.tf32.f32 "
        "{%0,%1,%2,%3}, {%4,%5,%6,%7}, {%8,%9}, {%0,%1,%2,%3};"
        : "+f"(c[0]), "+f"(c[1]), "+f"(c[2]), "+f"(c[3])
        : "r"(a[0]), "r"(a[1]), "r"(a[2]), "r"(a[3]), "r"(b[0]), "r"(b[1]));
}

// ---------------- graph preprocessing ----------------
__global__ void k_count(const int* __restrict__ ei, int E) {
    int e = blockIdx.x * blockDim.x + threadIdx.x;
    if (e == 0) g_total = 0;
    if (e >= E) return;
    atomicAdd(&g_deg[ei[(size_t)E + e]], 1);
}

__global__ void k_alloc(int N) {
    __shared__ int s[256];
    __shared__ int base;
    int tid = threadIdx.x;
    int i = blockIdx.x * 256 + tid;
    int d = (i < N) ? g_deg[i] : 0;
    if (i < N) g_dis[i] = rsqrtf((float)(d + 1));   // +1 self-loop
    s[tid] = d;
    __syncthreads();
    #pragma unroll
    for (int off = 1; off < 256; off <<= 1) {
        int v = (tid >= off) ? s[tid - off] : 0;
        __syncthreads();
        s[tid] += v;
        __syncthreads();
    }
    if (tid == 255) base = atomicAdd(&g_total, s[255]);
    __syncthreads();
    if (i < N) {
        int p = base + s[tid] - d;
        g_ptr[i] = p;
        g_cur[i] = p;
    }
}

__global__ void k_fill(const int* __restrict__ ei, int E) {
    int e = blockIdx.x * blockDim.x + threadIdx.x;
    if (e >= E) return;
    int r = ei[e];
    int c = ei[(size_t)E + e];
    int p = atomicAdd(&g_cur[c], 1);
    g_src[p] = r;
}

// ---------------- tf32 tensor-core GEMM: g_hwh = dis .* (A' @ W), fp16 out ----------------
// mode 0: A' = Aext (fp32, layer 1).  mode 1: A' = g_af (fp16 activated features).
// 128x128 block tile, 8 warps of 32x64.
#define WS_STRIDE 132
#define AS_STRIDE 36
#define SMEM_W_ELEMS (128 * WS_STRIDE)
#define SMEM_A_ELEMS (128 * AS_STRIDE)
#define GEMM_SMEM_BYTES ((SMEM_W_ELEMS + SMEM_A_ELEMS) * 4)

__global__ void __launch_bounds__(256, 2) gemm128(const float* __restrict__ Aext,
                                                  const float* __restrict__ W,
                                                  int mode, int N) {
    extern __shared__ float smem[];
    float* Ws = smem;                    // [k][n] stride 132
    float* As = smem + SMEM_W_ELEMS;     // [m][k] stride 36

    int tid  = threadIdx.x;
    int wid  = tid >> 5;
    int lane = tid & 31;
    int lr = lane >> 2;                  // 0..7
    int lc = lane & 3;                   // 0..3
    int warp_m = (wid & 3) * 32;
    int warp_n = (wid >> 2) * 64;
    int row0 = blockIdx.x * 128;

    #pragma unroll
    for (int i = tid * 4; i < 128 * 128; i += 1024) {
        float4 v = *(const float4*)&W[i];
        v.x = tf32r(v.x); v.y = tf32r(v.y); v.z = tf32r(v.z); v.w = tf32r(v.w);
        int r = i >> 7, c = i & 127;
        *(float4*)&Ws[r * WS_STRIDE + c] = v;
    }

    float acc[2][8][4];
    #pragma unroll
    for (int i = 0; i < 2; ++i)
        #pragma unroll
        for (int j = 0; j < 8; ++j)
            #pragma unroll
            for (int q = 0; q < 4; ++q) acc[i][j][q] = 0.f;

    for (int kb = 0; kb < 4; ++kb) {
        // stage A chunk: 128 rows x 32 k (4 quads per thread)
        #pragma unroll
        for (int j = 0; j < 4; ++j) {
            int f = tid + 256 * j;
            int r = f >> 3;
            int k4 = (f & 7) * 4;
            int grow = row0 + r;
            float4 v = make_float4(0.f, 0.f, 0.f, 0.f);
            if (mode) {
                if (grow < N) {
                    uint2 u = *(const uint2*)&g_af[(size_t)grow * 128 + kb * 32 + k4];
                    float2 f0 = __half22float2(*(const __half2*)&u.x);
                    float2 f1 = __half22float2(*(const __half2*)&u.y);
                    v = make_float4(f0.x, f0.y, f1.x, f1.y);
                }
            } else {
                if (grow < N) v = *(const float4*)&Aext[(size_t)grow * 128 + kb * 32 + k4];
            }
            v.x = tf32r(v.x); v.y = tf32r(v.y); v.z = tf32r(v.z); v.w = tf32r(v.w);
            *(float4*)&As[r * AS_STRIDE + k4] = v;
        }
        __syncthreads();

        #pragma unroll
        for (int ks = 0; ks < 4; ++ks) {
            unsigned af[2][4];
            #pragma unroll
            for (int i = 0; i < 2; ++i) {
                const float* ab = &As[(warp_m + i * 16 + lr) * AS_STRIDE + ks * 8 + lc];
                af[i][0] = __float_as_uint(ab[0]);
                af[i][1] = __float_as_uint(ab[8 * AS_STRIDE]);
                af[i][2] = __float_as_uint(ab[4]);
                af[i][3] = __float_as_uint(ab[8 * AS_STRIDE + 4]);
            }
            unsigned bf[8][2];
            #pragma unroll
            for (int j = 0; j < 8; ++j) {
                const float* bb = &Ws[(kb * 32 + ks * 8 + lc) * WS_STRIDE + warp_n + j * 8 + lr];
                bf[j][0] = __float_as_uint(bb[0]);
                bf[j][1] = __float_as_uint(bb[4 * WS_STRIDE]);
            }
            #pragma unroll
            for (int i = 0; i < 2; ++i)
                #pragma unroll
                for (int j = 0; j < 8; ++j)
                    mma_tf32(acc[i][j], af[i], bf[j]);
        }
        __syncthreads();
    }

    // epilogue: scale by dis[row], convert to half2, store
    #pragma unroll
    for (int i = 0; i < 2; ++i) {
        int r0i = row0 + warp_m + i * 16 + lr;
        int r1i = r0i + 8;
        float d0 = (r0i < N) ? g_dis[r0i] : 0.f;
        float d1 = (r1i < N) ? g_dis[r1i] : 0.f;
        #pragma unroll
        for (int j = 0; j < 8; ++j) {
            int col = warp_n + j * 8 + lc * 2;
            if (r0i < N)
                *(__half2*)&g_hwh[(size_t)r0i * 128 + col] =
                    __floats2half2_rn(acc[i][j][0] * d0, acc[i][j][1] * d0);
            if (r1i < N)
                *(__half2*)&g_hwh[(size_t)r1i * 128 + col] =
                    __floats2half2_rn(acc[i][j][2] * d1, acc[i][j][3] * d1);
        }
    }
}

// ---------------- SpMM width 128 (fp16 in, fused bias+relu+fp16 out) ----------------
// g_af[i] = half( relu( dis[i]*(hws[i] + sum hws[s]) + bias ) ),  hws prefolded with dis.
__device__ __forceinline__ void add_row(float4& s, const uint2* hp, size_t idx) {
    uint2 w = __ldg(&hp[idx]);
    float2 f0 = __half22float2(*(const __half2*)&w.x);
    float2 f1 = __half22float2(*(const __half2*)&w.y);
    s.x += f0.x; s.y += f0.y; s.z += f1.x; s.w += f1.y;
}

__global__ void spmm128(const float* __restrict__ bias, int N) {
    int warp = (blockIdx.x * blockDim.x + threadIdx.x) >> 5;
    if (warp >= N) return;
    int lane = threadIdx.x & 31;
    const uint2* hp = (const uint2*)g_hwh;       // 32 uint2 per row
    float4 s = make_float4(0.f, 0.f, 0.f, 0.f);
    add_row(s, hp, (size_t)warp * 32 + lane);    // self-loop term
    int beg = g_ptr[warp];
    int end = beg + g_deg[warp];
    int p = beg;
    for (; p + 3 < end; p += 4) {
        int s0 = __ldg(&g_src[p]);
        int s1 = __ldg(&g_src[p + 1]);
        int s2 = __ldg(&g_src[p + 2]);
        int s3 = __ldg(&g_src[p + 3]);
        add_row(s, hp, (size_t)s0 * 32 + lane);
        add_row(s, hp, (size_t)s1 * 32 + lane);
        add_row(s, hp, (size_t)s2 * 32 + lane);
        add_row(s, hp, (size_t)s3 * 32 + lane);
    }
    for (; p < end; ++p) {
        int s0 = __ldg(&g_src[p]);
        add_row(s, hp, (size_t)s0 * 32 + lane);
    }
    float di = g_dis[warp];
    float4 b4 = *(const float4*)&bias[lane * 4];
    float a0 = fmaxf(s.x * di + b4.x, 0.f);
    float a1 = fmaxf(s.y * di + b4.y, 0.f);
    float a2 = fmaxf(s.z * di + b4.z, 0.f);
    float a3 = fmaxf(s.w * di + b4.w, 0.f);
    __half2 h0 = __floats2half2_rn(a0, a1);
    __half2 h1 = __floats2half2_rn(a2, a3);
    uint2 u = make_uint2(*(unsigned*)&h0, *(unsigned*)&h1);
    *(uint2*)&g_af[(size_t)warp * 128 + lane * 4] = u;
}

// ---------------- layer 4 GEMM: g_h10[n] = dis[n] * (g_af[n] @ W_out) ----------------
__global__ void gemm_out(const float* __restrict__ W, int N) {
    __shared__ float Ws[128 * 10];
    int tid = threadIdx.x;
    for (int i = tid; i < 1280; i += 256) Ws[i] = W[i];
    __syncthreads();
    int n = blockIdx.x * 256 + tid;
    if (n >= N) return;
    float s[10];
    #pragma unroll
    for (int c = 0; c < 10; ++c) s[c] = 0.f;
    const uint2* a = (const uint2*)&g_af[(size_t)n * 128];
    #pragma unroll 4
    for (int k = 0; k < 128; k += 4) {
        uint2 u = a[k >> 2];
        float2 f0 = __half22float2(*(const __half2*)&u.x);
        float2 f1 = __half22float2(*(const __half2*)&u.y);
        const float* w0 = &Ws[k * 10];
        #pragma unroll
        for (int c = 0; c < 10; ++c)
            s[c] += f0.x * w0[c] + f0.y * w0[10 + c] + f1.x * w0[20 + c] + f1.y * w0[30 + c];
    }
    float dn = g_dis[n];
    float* o = g_h10 + (size_t)n * 10;
    #pragma unroll
    for (int c = 0; c < 10; ++c) o[c] = s[c] * dn;
}

// ---------------- SpMM width 10 (prefolded fp32) ----------------
__global__ void spmm10(int N) {
    int warp = (blockIdx.x * blockDim.x + threadIdx.x) >> 5;
    if (warp >= N) return;
    int lane = threadIdx.x & 31;
    int grp = lane / 10;
    int c = lane - grp * 10;
    bool active = lane < 30;
    float s = 0.f;
    if (active && grp == 0) s = g_h10[(size_t)warp * 10 + c];     // self-loop term
    int beg = g_ptr[warp];
    int m = g_deg[warp];
    for (int p = 0; p < m; p += 3) {
        int e = p + grp;
        if (active && e < m) {
            int src = __ldg(&g_src[beg + e]);
            s += g_h10[(size_t)src * 10 + c];
        }
    }
    float s1 = __shfl_sync(0xffffffffu, s, lane + 10);
    float s2 = __shfl_sync(0xffffffffu, s, lane + 20);
    if (lane < 10) g_a10[(size_t)warp * 10 + lane] = (s + s1 + s2) * g_dis[warp];
}

// ---------------- mean pooling ----------------
__device__ __forceinline__ int lower_bound_i(const int* a, int n, int key) {
    int lo = 0, hi = n;
    while (lo < hi) {
        int mid = (lo + hi) >> 1;
        if (a[mid] < key) lo = mid + 1; else hi = mid;
    }
    return lo;
}

__global__ void pool(const int* __restrict__ batch, const float* __restrict__ b_out,
                     float* __restrict__ out, int N) {
    __shared__ float sred[128];
    int g = blockIdx.x;
    int t = threadIdx.x;
    int lo = lower_bound_i(batch, N, g);
    int hi = lower_bound_i(batch, N, g + 1);
    float s = 0.f;
    if (t < 120) {
        int c = t / 12, sl = t % 12;
        for (int i = lo + sl; i < hi; i += 12) s += g_a10[(size_t)i * 10 + c];
    }
    sred[t] = s;
    __syncthreads();
    if (t < 10) {
        float tot = 0.f;
        #pragma unroll
        for (int j = 0; j < 12; ++j) tot += sred[t * 12 + j];
        float cnt = (float)(hi - lo);
        out[g * 10 + t] = (tot + cnt * b_out[t]) / fmaxf(cnt, 1.f);
    }
}

// ---------------- launcher ----------------
extern "C" void kernel_launch(void* const* d_in, const int* in_sizes, int n_in,
                              void* d_out, int out_size) {
    const float* x      = (const float*)d_in[0];
    const int*   ei     = (const int*)d_in[1];
    const int*   batch  = (const int*)d_in[2];
    const float* W_init = (const float*)d_in[3];
    const float* b_init = (const float*)d_in[4];
    const float* W_h0   = (const float*)d_in[5];
    const float* b_h0   = (const float*)d_in[6];
    const float* W_h1   = (const float*)d_in[7];
    const float* b_h1   = (const float*)d_in[8];
    const float* W_out  = (const float*)d_in[9];
    const float* b_out  = (const float*)d_in[10];
    float* out = (float*)d_out;

    int N = in_sizes[0] / 128;
    int E = in_sizes[1] / 2;

    int nb = (N + 255) / 256;
    int eb = (E + 255) / 256;
    int gb = (N + 127) / 128;
    int sb = (N + 7) / 8;

    static int* deg_ptr = nullptr;
    if (!deg_ptr) {
        cudaGetSymbolAddress((void**)&deg_ptr, g_deg);
        cudaFuncSetAttribute(gemm128, cudaFuncAttributeMaxDynamicSharedMemorySize, GEMM_SMEM_BYTES);
    }

    cudaMemsetAsync(deg_ptr, 0, (size_t)N * sizeof(int));
    k_count<<<eb, 256>>>(ei, E);
    k_alloc<<<nb, 256>>>(N);
    k_fill<<<eb, 256>>>(ei, E);

    // layer 1: x @ W_init -> propagate (+b_init, relu fused into spmm)
    gemm128<<<gb, 256, GEMM_SMEM_BYTES>>>(x, W_init, 0, N);
    spmm128<<<sb, 256>>>(b_init, N);
    // layer 2
    gemm128<<<gb, 256, GEMM_SMEM_BYTES>>>(nullptr, W_h0, 1, N);
    spmm128<<<sb, 256>>>(b_h0, N);
    // layer 3
    gemm128<<<gb, 256, GEMM_SMEM_BYTES>>>(nullptr, W_h1, 1, N);
    spmm128<<<sb, 256>>>(b_h1, N);
    // layer 4 (width 10) + propagate
    gemm_out<<<nb, 256>>>(W_out, N);
    spmm10<<<sb, 256>>>(N);
    // global mean pool (+ b_out)
    pool<<<512, 128>>>(batch, b_out, out, N);
}